// round 3
// baseline (speedup 1.0000x reference)
#include <cuda_runtime.h>
#include <math.h>

#define H      2048
#define HH     1024
#define NB     4
#define S      4096
#define NROWS  (NB*S)          // 16384 rows per matrix
#define SCHUNK 64
#define NCHUNK (S/SCHUNK)      // 64
#define TILE_R 16
#define MT     256             // main kernel threads

typedef unsigned long long ull;

// ---------------- packed f32x2 helpers ----------------------------------
__device__ __forceinline__ ull pack2(float lo, float hi) {
    ull r; asm("mov.b64 %0, {%1, %2};" : "=l"(r) : "f"(lo), "f"(hi)); return r;
}
__device__ __forceinline__ ull fma2(ull a, ull b, ull c) {
    ull d; asm("fma.rn.f32x2 %0, %1, %2, %3;" : "=l"(d) : "l"(a), "l"(b), "l"(c)); return d;
}
__device__ __forceinline__ float pairsum(ull a) {
    float lo, hi; asm("mov.b64 {%0, %1}, %2;" : "=f"(lo), "=f"(hi) : "l"(a)); return lo + hi;
}

// ---------------- device scratch (no allocation allowed) ----------------
__device__ float g_partial[NB*NCHUNK*H];   // fully overwritten each call
__device__ float g_h1p[NB*8*HH];
__device__ int   g_rank;
__device__ float g_At[2*16*H];             // kA^T at 0, vA^T at 16*H (selected rank)

// ---------------- kernel 1: chunked column sums of keys over S ----------
__global__ void k_mean_partial(const float* __restrict__ keys) {
    int b = blockIdx.y, c = blockIdx.x;
    const float4* base = (const float4*)(keys + ((size_t)b * S + (size_t)c * SCHUNK) * H);
    int t = threadIdx.x;                    // 512 threads cover H/4 float4 cols
    float4 a = make_float4(0.f, 0.f, 0.f, 0.f);
#pragma unroll 4
    for (int s = 0; s < SCHUNK; s++) {
        float4 v = __ldcg(base + (size_t)s * (H / 4) + t);
        a.x += v.x; a.y += v.y; a.z += v.z; a.w += v.w;
    }
    ((float4*)(g_partial + ((size_t)b * NCHUNK + c) * H))[t] = a;
}

// ---------------- kernel 2: partial hidden GEMV --------------------------
__global__ void k_gemv1(const float* __restrict__ w1) {
    __shared__ float sx[256];
    int jb = blockIdx.x, hc = blockIdx.y, b = blockIdx.z;
    int t = threadIdx.x;
    {
        int h = hc * 256 + t;
        float s0 = 0.f, s1 = 0.f, s2 = 0.f, s3 = 0.f;
#pragma unroll
        for (int c = 0; c < NCHUNK; c += 4) {
            s0 += g_partial[((size_t)b * NCHUNK + c + 0) * H + h];
            s1 += g_partial[((size_t)b * NCHUNK + c + 1) * H + h];
            s2 += g_partial[((size_t)b * NCHUNK + c + 2) * H + h];
            s3 += g_partial[((size_t)b * NCHUNK + c + 3) * H + h];
        }
        sx[t] = (s0 + s1 + s2 + s3) * (1.0f / (float)S);
    }
    __syncthreads();
    int j = jb * 256 + t;
    const float* wp = w1 + (size_t)(hc * 256) * HH + j;
    float a0 = 0.f, a1 = 0.f, a2 = 0.f, a3 = 0.f;
#pragma unroll 8
    for (int hh = 0; hh < 256; hh += 4) {
        a0 = fmaf(sx[hh + 0], wp[(size_t)(hh + 0) * HH], a0);
        a1 = fmaf(sx[hh + 1], wp[(size_t)(hh + 1) * HH], a1);
        a2 = fmaf(sx[hh + 2], wp[(size_t)(hh + 2) * HH], a2);
        a3 = fmaf(sx[hh + 3], wp[(size_t)(hh + 3) * HH], a3);
    }
    g_h1p[((size_t)b * 8 + hc) * HH + j] = (a0 + a1) + (a2 + a3);
}

// ---------------- kernel 3: relu + layer2 + sigmoid + rank select -------
__global__ void k_select(const float* __restrict__ b1, const float* __restrict__ w2,
                         const float* __restrict__ b2) {
    __shared__ float red[256];
    __shared__ float s_avg;
    int t = threadIdx.x;
    if (t == 0) s_avg = 0.f;
    __syncthreads();
    for (int b = 0; b < NB; b++) {
        float acc = 0.f;
#pragma unroll
        for (int k = 0; k < 4; k++) {
            int j = t + k * 256;
            float hv = b1[j];
#pragma unroll
            for (int hc = 0; hc < 8; hc++) hv += g_h1p[((size_t)b * 8 + hc) * HH + j];
            acc += fmaxf(hv, 0.f) * w2[j];
        }
        red[t] = acc;
        __syncthreads();
        for (int o = 128; o > 0; o >>= 1) {
            if (t < o) red[t] += red[t + o];
            __syncthreads();
        }
        if (t == 0) {
            float v = red[0] + b2[0];
            s_avg += 1.f / (1.f + expf(-v));
        }
        __syncthreads();
    }
    if (t == 0) {
        float avg = s_avg * 0.25f;
        g_rank = (int)(avg >= 0.3f) + (int)(avg >= 0.7f);
    }
}

// ---------------- kernel 4: transpose selected A's into g_At ------------
__global__ void k_prep(const float* __restrict__ kA0, const float* __restrict__ vA0,
                       const float* __restrict__ kA1, const float* __restrict__ vA1,
                       const float* __restrict__ kA2, const float* __restrict__ vA2) {
    int r = g_rank;
    const float* kA = (r == 0) ? kA0 : (r == 1) ? kA1 : kA2;
    const float* vA = (r == 0) ? vA0 : (r == 1) ? vA1 : vA2;
    int R = 4 << r;
    int total = R * H;
    for (int idx = blockIdx.x * blockDim.x + threadIdx.x; idx < total;
         idx += gridDim.x * blockDim.x) {
        int j = idx / H, h = idx - j * H;          // g_At[j*H + h] = A[h*R + j]
        g_At[idx]          = kA[(size_t)h * R + j];
        g_At[16 * H + idx] = vA[(size_t)h * R + j];
    }
}

// ---------------- main body: out = x + (x @ A) @ B ----------------------
template <int R>
__device__ __forceinline__ void main_body(
    const float* __restrict__ src, const float* __restrict__ At,
    const float* __restrict__ Bw, float* __restrict__ dst,
    int row0, float* s_P2) {

    int tid = threadIdx.x;
    int w = tid >> 5, l = tid & 31;

    // ---- Phase 1: P[row][j] = row . A^T[j]; warp handles RPW rows -------
    constexpr int RPW = (R <= 8) ? 2 : 1;
    constexpr int NPASS = TILE_R / (8 * RPW);
#pragma unroll
    for (int ps = 0; ps < NPASS; ps++) {
        int rbase = ps * 8 * RPW + w * RPW;
        ull acc[RPW][R];
#pragma unroll
        for (int i = 0; i < RPW; i++)
#pragma unroll
            for (int j = 0; j < R; j++) acc[i][j] = 0ull;

#pragma unroll 2
        for (int h4 = l; h4 < H / 4; h4 += 32) {
            ull kx[RPW], ky[RPW];
#pragma unroll
            for (int i = 0; i < RPW; i++) {
                float4 v = __ldcg((const float4*)(src + (size_t)(row0 + rbase + i) * H + h4 * 4));
                kx[i] = pack2(v.x, v.y); ky[i] = pack2(v.z, v.w);
            }
#pragma unroll
            for (int j = 0; j < R; j++) {
                float4 av = __ldg((const float4*)(At + (size_t)j * H + h4 * 4));
                ull ax = pack2(av.x, av.y), ay = pack2(av.z, av.w);
#pragma unroll
                for (int i = 0; i < RPW; i++) {
                    acc[i][j] = fma2(kx[i], ax, acc[i][j]);
                    acc[i][j] = fma2(ky[i], ay, acc[i][j]);
                }
            }
        }
#pragma unroll
        for (int i = 0; i < RPW; i++)
#pragma unroll
            for (int j = 0; j < R; j++) {
                float v = pairsum(acc[i][j]);
#pragma unroll
                for (int o = 16; o > 0; o >>= 1) v += __shfl_xor_sync(0xffffffffu, v, o);
                if (l == 0) *(ull*)(s_P2 + ((rbase + i) * R + j) * 2) = pack2(v, v);
            }
    }
    __syncthreads();

    // ---- Phase 2: out[row][h] = src[row][h] + sum_j P[row][j]*B[j][h] ---
    // Two column halves; B registers hoisted per half; 2-row groups.
#pragma unroll
    for (int cs = 0; cs < 2; cs++) {
        int col4 = tid + cs * MT;                 // float4 column in [0, 512)
        ull b0[R], b1[R];
#pragma unroll
        for (int j = 0; j < R; j++) {
            float4 bv = __ldg((const float4*)(Bw + (size_t)j * H + col4 * 4));
            b0[j] = pack2(bv.x, bv.y); b1[j] = pack2(bv.z, bv.w);
        }
#pragma unroll 2
        for (int g = 0; g < TILE_R; g += 2) {
            float4 v0 = __ldcg((const float4*)(src + (size_t)(row0 + g + 0) * H + col4 * 4));
            float4 v1 = __ldcg((const float4*)(src + (size_t)(row0 + g + 1) * H + col4 * 4));
            ull o0x = pack2(v0.x, v0.y), o0y = pack2(v0.z, v0.w);
            ull o1x = pack2(v1.x, v1.y), o1y = pack2(v1.z, v1.w);
#pragma unroll
            for (int j = 0; j < R; j++) {
                ull p0 = *(const ull*)(s_P2 + ((g + 0) * R + j) * 2);
                ull p1 = *(const ull*)(s_P2 + ((g + 1) * R + j) * 2);
                o0x = fma2(b0[j], p0, o0x); o0y = fma2(b1[j], p0, o0y);
                o1x = fma2(b0[j], p1, o1x); o1y = fma2(b1[j], p1, o1y);
            }
            float r0, r1, r2, r3, r4, r5, r6, r7;
            asm("mov.b64 {%0, %1}, %2;" : "=f"(r0), "=f"(r1) : "l"(o0x));
            asm("mov.b64 {%0, %1}, %2;" : "=f"(r2), "=f"(r3) : "l"(o0y));
            asm("mov.b64 {%0, %1}, %2;" : "=f"(r4), "=f"(r5) : "l"(o1x));
            asm("mov.b64 {%0, %1}, %2;" : "=f"(r6), "=f"(r7) : "l"(o1y));
            __stcg((float4*)(dst + (size_t)(row0 + g + 0) * H + col4 * 4),
                   make_float4(r0, r1, r2, r3));
            __stcg((float4*)(dst + (size_t)(row0 + g + 1) * H + col4 * 4),
                   make_float4(r4, r5, r6, r7));
        }
    }
}

// single kernel, uniform branch on g_rank — no dead launches
__global__ void __launch_bounds__(MT, 4)
k_main_all(const float* __restrict__ keys, const float* __restrict__ values,
           const float* __restrict__ kB0, const float* __restrict__ kB1,
           const float* __restrict__ kB2,
           const float* __restrict__ vB0, const float* __restrict__ vB1,
           const float* __restrict__ vB2,
           float* __restrict__ out) {
    __shared__ float s_P2[TILE_R * 16 * 2];
    int r = g_rank;
    int row0 = blockIdx.x * TILE_R;
    const float* src; const float* At; float* dst; bool is_k;
    if (row0 < NROWS) { src = keys;   At = g_At;          dst = out;                       is_k = true; }
    else { row0 -= NROWS; src = values; At = g_At + 16 * H; dst = out + (size_t)NROWS * H; is_k = false; }

    if (r == 0) {
        const float* Bw = is_k ? kB0 : vB0;
        main_body<4>(src, At, Bw, dst, row0, s_P2);
    } else if (r == 1) {
        const float* Bw = is_k ? kB1 : vB1;
        main_body<8>(src, At, Bw, dst, row0, s_P2);
    } else {
        const float* Bw = is_k ? kB2 : vB2;
        main_body<16>(src, At, Bw, dst, row0, s_P2);
    }
}

// ---------------- launch -------------------------------------------------
extern "C" void kernel_launch(void* const* d_in, const int* in_sizes, int n_in,
                              void* d_out, int out_size) {
    const float* keys   = (const float*)d_in[0];
    const float* values = (const float*)d_in[1];
    const float* w1     = (const float*)d_in[2];
    const float* b1     = (const float*)d_in[3];
    const float* w2     = (const float*)d_in[4];
    const float* b2     = (const float*)d_in[5];
    const float* kA0 = (const float*)d_in[6];  const float* kB0 = (const float*)d_in[7];
    const float* vA0 = (const float*)d_in[8];  const float* vB0 = (const float*)d_in[9];
    const float* kA1 = (const float*)d_in[10]; const float* kB1 = (const float*)d_in[11];
    const float* vA1 = (const float*)d_in[12]; const float* vB1 = (const float*)d_in[13];
    const float* kA2 = (const float*)d_in[14]; const float* kB2 = (const float*)d_in[15];
    const float* vA2 = (const float*)d_in[16]; const float* vB2 = (const float*)d_in[17];
    float* out = (float*)d_out;

    k_mean_partial<<<dim3(NCHUNK, NB), 512>>>(keys);
    k_gemv1<<<dim3(4, 8, NB), 256>>>(w1);
    k_select<<<1, 256>>>(b1, w2, b2);
    k_prep<<<32, 256>>>(kA0, vA0, kA1, vA1, kA2, vA2);

    const int grid = (2 * NROWS) / TILE_R;   // 2048 CTAs
    k_main_all<<<grid, MT>>>(keys, values, kB0, kB1, kB2, vB0, vB1, vB2, out);
}